// round 5
// baseline (speedup 1.0000x reference)
#include <cuda_runtime.h>
#include <cstdint>

// ---------------------------------------------------------------------------
// GraphSage (eval) on GB300 — round 5: fp16 mma.sync (m16n8k16) GEMMs,
// cp.async 3-stage pipeline, split-A conv (no h copy into hcat).
// ---------------------------------------------------------------------------

#define NMAX 50000
#define EMAX 1000000
#define FDIM 256

__device__ __align__(16) float g_h[NMAX * FDIM];
__device__ __align__(16) float g_hn[NMAX * FDIM];
__device__ __align__(16) float g_tmp[NMAX * 304];
__device__ __align__(16) float g_hagg[NMAX * FDIM];
__device__ int g_deg[NMAX];
__device__ int g_rowoff[NMAX + 1];
__device__ int g_cursor[NMAX];
__device__ int g_adj[EMAX];

// ---------------------------------------------------------------------------
// CSR build
__global__ void zero_deg_kernel(int n) {
    int i = blockIdx.x * blockDim.x + threadIdx.x;
    if (i < n) g_deg[i] = 0;
}
__global__ void count_deg_kernel(const int* __restrict__ dst, int E) {
    int i = blockIdx.x * blockDim.x + threadIdx.x;
    int stride = gridDim.x * blockDim.x;
    for (; i < E; i += stride) atomicAdd(&g_deg[dst[i]], 1);
}
__global__ void scan_kernel(int n) {
    __shared__ int warp_sums[32];
    __shared__ int s_carry;
    int t = threadIdx.x;
    if (t == 0) s_carry = 0;
    __syncthreads();
    for (int base = 0; base < n; base += 1024) {
        int i = base + t;
        int v = (i < n) ? g_deg[i] : 0;
        int x = v;
        #pragma unroll
        for (int off = 1; off < 32; off <<= 1) {
            int y = __shfl_up_sync(0xffffffffu, x, off);
            if ((t & 31) >= off) x += y;
        }
        if ((t & 31) == 31) warp_sums[t >> 5] = x;
        __syncthreads();
        if (t < 32) {
            int w = warp_sums[t];
            int xx = w;
            #pragma unroll
            for (int off = 1; off < 32; off <<= 1) {
                int y = __shfl_up_sync(0xffffffffu, xx, off);
                if (t >= off) xx += y;
            }
            warp_sums[t] = xx - w;
        }
        __syncthreads();
        int incl = x + warp_sums[t >> 5];
        int excl = incl - v + s_carry;
        if (i < n) { g_rowoff[i] = excl; g_cursor[i] = excl; }
        __syncthreads();
        if (t == 1023) s_carry += incl;
        __syncthreads();
    }
    if (t == 0) g_rowoff[n] = s_carry;
}
__global__ void scatter_kernel(const int* __restrict__ src,
                               const int* __restrict__ dst, int E) {
    int i = blockIdx.x * blockDim.x + threadIdx.x;
    int stride = gridDim.x * blockDim.x;
    for (; i < E; i += stride) {
        int p = atomicAdd(&g_cursor[dst[i]], 1);
        g_adj[p] = src[i];
    }
}

// aggregate: hagg[n] = mean over in-neighbors of h
__global__ void aggregate_kernel(int N) {
    int node = blockIdx.x * blockDim.y + threadIdx.y;
    if (node >= N) return;
    int j = threadIdx.x;  // 0..63
    int beg = g_rowoff[node], end = g_rowoff[node + 1];
    float4 acc = make_float4(0.f, 0.f, 0.f, 0.f);
    for (int e = beg; e < end; e++) {
        int s = g_adj[e];
        float4 v = *(const float4*)&g_h[(size_t)s * FDIM + j * 4];
        acc.x += v.x; acc.y += v.y; acc.z += v.z; acc.w += v.w;
    }
    int d = end - beg;
    float inv = 1.0f / (float)(d > 1 ? d : 1);
    float4 o = make_float4(acc.x * inv, acc.y * inv, acc.z * inv, acc.w * inv);
    *(float4*)&g_hagg[(size_t)node * FDIM + j * 4] = o;
}

// L2-normalize rows (F = 256)
__global__ void l2norm_kernel(const float* __restrict__ in,
                              float* __restrict__ out, int N) {
    int n = blockIdx.x;
    int t = threadIdx.x;
    float v = in[(size_t)n * FDIM + t];
    float ss = v * v;
    #pragma unroll
    for (int o = 16; o > 0; o >>= 1) ss += __shfl_xor_sync(0xffffffffu, ss, o);
    __shared__ float ws[8];
    __shared__ float s_tot;
    if ((t & 31) == 0) ws[t >> 5] = ss;
    __syncthreads();
    if (t == 0) {
        float x = 0.f;
        #pragma unroll
        for (int i = 0; i < 8; i++) x += ws[i];
        s_tot = x;
    }
    __syncthreads();
    float norm = sqrtf(s_tot);
    out[(size_t)n * FDIM + t] = v / fmaxf(norm, 1e-6f);
}

// ---------------------------------------------------------------------------
// fp16 mma.sync GEMM with cp.async 3-stage pipeline (fp32 in smem, cvt at
// fragment load). C[M,Ncols] = act(A[M,K] @ W[Ncols,K]^T + bias) [+ addsrc]
// CTA 128x128, K-chunk 32, 256 threads (8 warps 2x4), warp tile 64x32.
// A may be split at column kSplit: k < kSplit from A, k >= kSplit from A2.

__device__ __forceinline__ uint32_t f16x2(float lo, float hi) {
    uint32_t r;
    asm("cvt.rn.f16x2.f32 %0, %1, %2;" : "=r"(r) : "f"(hi), "f"(lo));
    return r;
}
__device__ __forceinline__ void mma_f16(float* c, const uint32_t* a,
                                        const uint32_t* b) {
    asm volatile(
        "mma.sync.aligned.m16n8k16.row.col.f32.f16.f16.f32 "
        "{%0,%1,%2,%3}, {%4,%5,%6,%7}, {%8,%9}, {%0,%1,%2,%3};"
        : "+f"(c[0]), "+f"(c[1]), "+f"(c[2]), "+f"(c[3])
        : "r"(a[0]), "r"(a[1]), "r"(a[2]), "r"(a[3]), "r"(b[0]), "r"(b[1]));
}
__device__ __forceinline__ void cp16(uint32_t dst, const void* src, int nbytes) {
    asm volatile("cp.async.cg.shared.global [%0], [%1], 16, %2;"
                 :: "r"(dst), "l"(src), "r"(nbytes) : "memory");
}
__device__ __forceinline__ void cp_commit() {
    asm volatile("cp.async.commit_group;" ::: "memory");
}
__device__ __forceinline__ void cp_wait1() {
    asm volatile("cp.async.wait_group 1;" ::: "memory");
}

#define GBM 128
#define GBN 128
#define GBK 32
#define GST 36
#define SFLOATS (128 * GST)
#define STAGE_FLOATS (2 * SFLOATS)
#define NSTAGE 3

extern __shared__ float sm_dyn[];

__global__ __launch_bounds__(256, 2)
void gemm_mma(const float* __restrict__ A, const float* __restrict__ A2,
              int kSplit, int lda,
              const int* __restrict__ gidx,
              const float* __restrict__ W,
              const float* __restrict__ bias,
              const float* __restrict__ addsrc,
              float* __restrict__ C, int ldc,
              int M, int Ncols, int K, int act)
{
    const int tid = threadIdx.x;
    const int wid = tid >> 5;
    const int lane = tid & 31;
    const int bm = blockIdx.x * GBM;
    const int bn = blockIdx.y * GBN;
    const int warp_m = (wid >> 2) * 64;
    const int warp_n = (wid & 3) * 32;

    const int ldRow = tid >> 1;
    const int kHalf = tid & 1;

    const bool aValid = (bm + ldRow < M);
    int aR = aValid ? (bm + ldRow) : 0;
    if (gidx) aR = __ldg(&gidx[aValid ? bm + ldRow : 0]);
    const float* aBase = A + (size_t)aR * lda;
    const float* aBase2 = A2 ? (A2 + (size_t)aR * lda) : nullptr;
    const bool bValid = (bn + ldRow < Ncols);
    const float* bBase = W + (size_t)(bValid ? bn + ldRow : 0) * K;

    const uint32_t smemBase = (uint32_t)__cvta_generic_to_shared(sm_dyn);
    const int nCh = (K + GBK - 1) / GBK;

    float acc[4][4][4];
    #pragma unroll
    for (int mt = 0; mt < 4; mt++)
        #pragma unroll
        for (int nt = 0; nt < 4; nt++)
            #pragma unroll
            for (int j = 0; j < 4; j++) acc[mt][nt][j] = 0.f;

    auto issueStage = [&](int ch, int stage) {
        if (ch < nCh) {
            const int k0 = ch * GBK + kHalf * 16;
            const uint32_t dRow =
                smemBase + (stage * STAGE_FLOATS + ldRow * GST + kHalf * 16) * 4;
            const uint32_t dRowB = dRow + SFLOATS * 4;
            #pragma unroll
            for (int j = 0; j < 4; j++) {
                const int c = k0 + j * 4;
                const int rem = K - c;
                const int nbF = (rem >= 4) ? 16 : (rem > 0 ? rem * 4 : 0);
                const float* ap = (c < kSplit) ? (aBase + c)
                                               : (aBase2 + (c - kSplit));
                cp16(dRow + j * 16, ap, aValid ? nbF : 0);
                cp16(dRowB + j * 16, bBase + c, bValid ? nbF : 0);
            }
        }
        cp_commit();
    };

    auto computeStage = [&](int stage) {
        const float* As = sm_dyn + stage * STAGE_FLOATS;
        const float* Bs = As + SFLOATS;
        #pragma unroll
        for (int p = 0; p < 2; p++) {            // two k16 steps per chunk
            const int kc = p * 16 + 2 * (lane & 3);
            uint32_t af[4][4], bf[4][2];
            #pragma unroll
            for (int mt = 0; mt < 4; mt++) {
                const int r0 = warp_m + mt * 16 + (lane >> 2);
                const float2 v0 = *(const float2*)&As[r0 * GST + kc];
                const float2 v1 = *(const float2*)&As[(r0 + 8) * GST + kc];
                const float2 v2 = *(const float2*)&As[r0 * GST + kc + 8];
                const float2 v3 = *(const float2*)&As[(r0 + 8) * GST + kc + 8];
                af[mt][0] = f16x2(v0.x, v0.y);
                af[mt][1] = f16x2(v1.x, v1.y);
                af[mt][2] = f16x2(v2.x, v2.y);
                af[mt][3] = f16x2(v3.x, v3.y);
            }
            #pragma unroll
            for (int nt = 0; nt < 4; nt++) {
                const int c0 = warp_n + nt * 8 + (lane >> 2);
                const float2 w0 = *(const float2*)&Bs[c0 * GST + kc];
                const float2 w1 = *(const float2*)&Bs[c0 * GST + kc + 8];
                bf[nt][0] = f16x2(w0.x, w0.y);
                bf[nt][1] = f16x2(w1.x, w1.y);
            }
            #pragma unroll
            for (int mt = 0; mt < 4; mt++)
                #pragma unroll
                for (int nt = 0; nt < 4; nt++)
                    mma_f16(acc[mt][nt], af[mt], bf[nt]);
        }
    };

    issueStage(0, 0);
    issueStage(1, 1);
    for (int ch = 0; ch < nCh; ch++) {
        cp_wait1();
        __syncthreads();
        computeStage(ch % NSTAGE);
        issueStage(ch + 2, (ch + 2) % NSTAGE);
    }

    // ---- epilogue ----
    #pragma unroll
    for (int mt = 0; mt < 4; mt++) {
        int row = bm + warp_m + mt * 16 + (lane >> 2);
        #pragma unroll
        for (int nt = 0; nt < 4; nt++) {
            int col = bn + warp_n + nt * 8 + 2 * (lane & 3);
            if (col >= Ncols) continue;
            float b0 = __ldg(&bias[col]);
            float b1 = __ldg(&bias[col + 1]);
            #pragma unroll
            for (int half = 0; half < 2; half++) {
                int r = row + half * 8;
                if (r >= M) continue;
                float v0 = acc[mt][nt][half * 2 + 0] + b0;
                float v1 = acc[mt][nt][half * 2 + 1] + b1;
                if (act) {
                    v0 = (v0 > 0.f) ? v0 : 0.1f * v0;
                    v1 = (v1 > 0.f) ? v1 : 0.1f * v1;
                }
                if (addsrc) {
                    const float2 s = *(const float2*)&addsrc[(size_t)r * ldc + col];
                    v0 += s.x; v1 += s.y;
                }
                *(float2*)&C[(size_t)r * ldc + col] = make_float2(v0, v1);
            }
        }
    }
}

// ---------------------------------------------------------------------------
extern "C" void kernel_launch(void* const* d_in, const int* in_sizes, int n_in,
                              void* d_out, int out_size) {
    const int*   node_ids = (const int*)  d_in[0];
    const float* content  = (const float*)d_in[1];
    const int*   src      = (const int*)  d_in[2];
    const int*   dst      = (const int*)  d_in[3];
    const float* emb      = (const float*)d_in[4];
    const float* W_exp    = (const float*)d_in[5];
    const float* b_exp    = (const float*)d_in[6];
    const float* W_p1     = (const float*)d_in[7];
    const float* b_p1     = (const float*)d_in[8];
    const float* W_p2     = (const float*)d_in[9];
    const float* b_p2     = (const float*)d_in[10];
    const float* W_conv   = (const float*)d_in[11];
    const float* b_conv   = (const float*)d_in[12];
    const float* Wo1      = (const float*)d_in[13];
    const float* bo1      = (const float*)d_in[14];
    const float* Wo2      = (const float*)d_in[15];
    const float* bo2      = (const float*)d_in[16];
    float* out = (float*)d_out;

    const int N  = in_sizes[0];
    const int E  = in_sizes[2];
    const int NC = in_sizes[1] / N;                 // 300
    const int ED = in_sizes[4] / (N + 1);           // 64
    const int F  = in_sizes[5] / ED;                // 256
    const int L  = in_sizes[11] / (F * 2 * F);      // 3

    float *p_h, *p_hn, *p_tmp, *p_hagg;
    cudaGetSymbolAddress((void**)&p_h, g_h);
    cudaGetSymbolAddress((void**)&p_hn, g_hn);
    cudaGetSymbolAddress((void**)&p_tmp, g_tmp);
    cudaGetSymbolAddress((void**)&p_hagg, g_hagg);

    const int SMEM = NSTAGE * STAGE_FLOATS * 4;  // 110592 B
    cudaFuncSetAttribute(gemm_mma, cudaFuncAttributeMaxDynamicSharedMemorySize, SMEM);

    // ---- CSR build ----
    zero_deg_kernel<<<(N + 255) / 256, 256>>>(N);
    count_deg_kernel<<<1024, 256>>>(dst, E);
    scan_kernel<<<1, 1024>>>(N);
    scatter_kernel<<<1024, 256>>>(src, dst, E);

    const int gmx = (N + GBM - 1) / GBM;
    auto gy = [](int n) { return (n + GBN - 1) / GBN; };

    // ---- initial representation ----
    gemm_mma<<<dim3(gmx, gy(F)), 256, SMEM>>>(
        emb, nullptr, 1 << 30, ED, node_ids, W_exp, b_exp, nullptr,
        p_h, F, N, F, ED, 1);
    gemm_mma<<<dim3(gmx, gy(NC)), 256, SMEM>>>(
        content, nullptr, 1 << 30, NC, nullptr, W_p1, b_p1, nullptr,
        p_tmp, NC, N, NC, NC, 1);
    gemm_mma<<<dim3(gmx, gy(F)), 256, SMEM>>>(
        p_tmp, nullptr, 1 << 30, NC, nullptr, W_p2, b_p2, p_h,
        p_h, F, N, F, NC, 1);

    // ---- layers ----
    for (int i = 0; i < L; i++) {
        dim3 aggBlk(64, 4);
        aggregate_kernel<<<(N + 3) / 4, aggBlk>>>(N);

        int act = (i < L - 1) ? 1 : 0;
        // conv A = [h | hagg] via split pointers
        gemm_mma<<<dim3(gmx, gy(F)), 256, SMEM>>>(
            p_h, p_hagg, F, F, nullptr,
            W_conv + (size_t)i * F * 2 * F, b_conv + (size_t)i * F,
            nullptr, p_hn, F, N, F, 2 * F, act);

        if (i < L - 1) {
            l2norm_kernel<<<N, F>>>(p_hn, p_hn, N);
            gemm_mma<<<dim3(gmx, gy(F)), 256, SMEM>>>(
                p_hn, nullptr, 1 << 30, F, nullptr,
                Wo1 + (size_t)i * F * F, bo1 + (size_t)i * F,
                nullptr, p_tmp, F, N, F, F, 1);
            gemm_mma<<<dim3(gmx, gy(F)), 256, SMEM>>>(
                p_tmp, nullptr, 1 << 30, F, nullptr,
                Wo2 + (size_t)i * F * F, bo2 + (size_t)i * F,
                nullptr, p_h, F, N, F, F, 0);
        } else {
            l2norm_kernel<<<N, F>>>(p_hn, out, N);
        }
    }
}

// round 6
// speedup vs baseline: 1.6549x; 1.6549x over previous
#include <cuda_runtime.h>
#include <cuda_fp16.h>
#include <cstdint>

// ---------------------------------------------------------------------------
// GraphSage (eval) on GB300 — round 6: full fp16 datapath.
// GEMM: cp.async fp16 tiles + XOR-swizzled smem + ldmatrix + mma m16n8k16.
// Aggregation gathers fp16 rows (half traffic), fp32 accumulate.
// ---------------------------------------------------------------------------

#define NMAX 50000
#define EMAX 1000000
#define FDIM 256
#define PADC 304

// fp32 buffers
__device__ __align__(16) float g_h[NMAX * FDIM];
__device__ __align__(16) float g_hn[NMAX * FDIM];
// fp16 buffers (zero-initialized at module load; pad columns never written)
__device__ __align__(16) __half g_h16[NMAX * FDIM];
__device__ __align__(16) __half g_hn16[NMAX * FDIM];
__device__ __align__(16) __half g_hagg16[NMAX * FDIM];
__device__ __align__(16) __half g_tmp16[NMAX * PADC];
__device__ __align__(16) __half g_emb16[(NMAX + 1) * 64];
__device__ __align__(16) __half g_c16[NMAX * PADC];
__device__ __align__(16) __half g_we16[256 * 64];
__device__ __align__(16) __half g_wp1[304 * PADC];
__device__ __align__(16) __half g_wp2[256 * PADC];
__device__ __align__(16) __half g_wc16[3 * 256 * 512];
__device__ __align__(16) __half g_wo1[2 * 256 * 256];
__device__ __align__(16) __half g_wo2[2 * 256 * 256];
// CSR
__device__ int g_deg[NMAX];
__device__ int g_rowoff[NMAX + 1];
__device__ int g_cursor[NMAX];
__device__ int g_adj[EMAX];

// ---------------------------------------------------------------------------
__global__ void cvt_kernel(const float* __restrict__ src, int lds,
                           __half* __restrict__ dst, int ldd,
                           int rows, int cols) {
    int total = rows * cols;
    for (int i = blockIdx.x * blockDim.x + threadIdx.x; i < total;
         i += gridDim.x * blockDim.x) {
        int r = i / cols, c = i - r * cols;
        dst[(size_t)r * ldd + c] = __float2half_rn(src[(size_t)r * lds + c]);
    }
}

// ---------------------------------------------------------------------------
// CSR build
__global__ void zero_deg_kernel(int n) {
    int i = blockIdx.x * blockDim.x + threadIdx.x;
    if (i < n) g_deg[i] = 0;
}
__global__ void count_deg_kernel(const int* __restrict__ dst, int E) {
    int i = blockIdx.x * blockDim.x + threadIdx.x;
    int stride = gridDim.x * blockDim.x;
    for (; i < E; i += stride) atomicAdd(&g_deg[dst[i]], 1);
}
__global__ void scan_kernel(int n) {
    __shared__ int warp_sums[32];
    __shared__ int s_carry;
    int t = threadIdx.x;
    if (t == 0) s_carry = 0;
    __syncthreads();
    for (int base = 0; base < n; base += 1024) {
        int i = base + t;
        int v = (i < n) ? g_deg[i] : 0;
        int x = v;
        #pragma unroll
        for (int off = 1; off < 32; off <<= 1) {
            int y = __shfl_up_sync(0xffffffffu, x, off);
            if ((t & 31) >= off) x += y;
        }
        if ((t & 31) == 31) warp_sums[t >> 5] = x;
        __syncthreads();
        if (t < 32) {
            int w = warp_sums[t];
            int xx = w;
            #pragma unroll
            for (int off = 1; off < 32; off <<= 1) {
                int y = __shfl_up_sync(0xffffffffu, xx, off);
                if (t >= off) xx += y;
            }
            warp_sums[t] = xx - w;
        }
        __syncthreads();
        int incl = x + warp_sums[t >> 5];
        int excl = incl - v + s_carry;
        if (i < n) { g_rowoff[i] = excl; g_cursor[i] = excl; }
        __syncthreads();
        if (t == 1023) s_carry += incl;
        __syncthreads();
    }
    if (t == 0) g_rowoff[n] = s_carry;
}
__global__ void scatter_kernel(const int* __restrict__ src,
                               const int* __restrict__ dst, int E) {
    int i = blockIdx.x * blockDim.x + threadIdx.x;
    int stride = gridDim.x * blockDim.x;
    for (; i < E; i += stride) {
        int p = atomicAdd(&g_cursor[dst[i]], 1);
        g_adj[p] = src[i];
    }
}

// aggregate: hagg16[n] = fp16(mean over in-neighbors of h16)
__global__ void aggregate_kernel(int N) {
    int node = blockIdx.x * blockDim.y + threadIdx.y;
    if (node >= N) return;
    int j = threadIdx.x;  // 0..63, handles 4 fp16 at col j*4
    int beg = g_rowoff[node], end = g_rowoff[node + 1];
    float4 acc = make_float4(0.f, 0.f, 0.f, 0.f);
    for (int e = beg; e < end; e++) {
        int s = g_adj[e];
        const __half2* row = (const __half2*)&g_h16[(size_t)s * FDIM];
        float2 a = __half22float2(row[j * 2]);
        float2 b = __half22float2(row[j * 2 + 1]);
        acc.x += a.x; acc.y += a.y; acc.z += b.x; acc.w += b.y;
    }
    int d = end - beg;
    float inv = 1.0f / (float)(d > 1 ? d : 1);
    __half2* o = (__half2*)&g_hagg16[(size_t)node * FDIM];
    o[j * 2]     = __floats2half2_rn(acc.x * inv, acc.y * inv);
    o[j * 2 + 1] = __floats2half2_rn(acc.z * inv, acc.w * inv);
}

// L2-normalize rows: fp32 in -> fp16 out
__global__ void l2norm16_kernel(const float* __restrict__ in,
                                __half* __restrict__ out, int N) {
    int n = blockIdx.x;
    int t = threadIdx.x;
    float v = in[(size_t)n * FDIM + t];
    float ss = v * v;
    #pragma unroll
    for (int o = 16; o > 0; o >>= 1) ss += __shfl_xor_sync(0xffffffffu, ss, o);
    __shared__ float ws[8];
    __shared__ float s_tot;
    if ((t & 31) == 0) ws[t >> 5] = ss;
    __syncthreads();
    if (t == 0) {
        float x = 0.f;
        #pragma unroll
        for (int i = 0; i < 8; i++) x += ws[i];
        s_tot = x;
    }
    __syncthreads();
    float norm = sqrtf(s_tot);
    out[(size_t)n * FDIM + t] = __float2half_rn(v / fmaxf(norm, 1e-6f));
}
// L2-normalize rows: fp32 in -> fp32 out (final layer)
__global__ void l2norm_kernel(const float* __restrict__ in,
                              float* __restrict__ out, int N) {
    int n = blockIdx.x;
    int t = threadIdx.x;
    float v = in[(size_t)n * FDIM + t];
    float ss = v * v;
    #pragma unroll
    for (int o = 16; o > 0; o >>= 1) ss += __shfl_xor_sync(0xffffffffu, ss, o);
    __shared__ float ws[8];
    __shared__ float s_tot;
    if ((t & 31) == 0) ws[t >> 5] = ss;
    __syncthreads();
    if (t == 0) {
        float x = 0.f;
        #pragma unroll
        for (int i = 0; i < 8; i++) x += ws[i];
        s_tot = x;
    }
    __syncthreads();
    float norm = sqrtf(s_tot);
    out[(size_t)n * FDIM + t] = v / fmaxf(norm, 1e-6f);
}

// ---------------------------------------------------------------------------
// fp16 GEMM: C[M,Ncols] = act(A16[M,K] @ W16[Ncols,K]^T + bias) [+ addsrc]
// CTA 128x128, K-chunk 64 (128B fp16 rows), 3-stage cp.async, ldmatrix frags.
// A split at kSplit (multiple of 64): k<kSplit from A, else A2.

__device__ __forceinline__ void mma_f16(float* c, const uint32_t* a,
                                        const uint32_t* b) {
    asm volatile(
        "mma.sync.aligned.m16n8k16.row.col.f32.f16.f16.f32 "
        "{%0,%1,%2,%3}, {%4,%5,%6,%7}, {%8,%9}, {%0,%1,%2,%3};"
        : "+f"(c[0]), "+f"(c[1]), "+f"(c[2]), "+f"(c[3])
        : "r"(a[0]), "r"(a[1]), "r"(a[2]), "r"(a[3]), "r"(b[0]), "r"(b[1]));
}
__device__ __forceinline__ void ldsm4(uint32_t* r, uint32_t addr) {
    asm volatile("ldmatrix.sync.aligned.m8n8.x4.shared.b16 {%0,%1,%2,%3}, [%4];"
                 : "=r"(r[0]), "=r"(r[1]), "=r"(r[2]), "=r"(r[3]) : "r"(addr));
}
__device__ __forceinline__ void cp16(uint32_t dst, const void* src, int nbytes) {
    asm volatile("cp.async.cg.shared.global [%0], [%1], 16, %2;"
                 :: "r"(dst), "l"(src), "r"(nbytes) : "memory");
}
__device__ __forceinline__ void cp_commit() {
    asm volatile("cp.async.commit_group;" ::: "memory");
}
__device__ __forceinline__ void cp_wait1() {
    asm volatile("cp.async.wait_group 1;" ::: "memory");
}

#define GBM 128
#define GBN 128
#define GBK 64
#define TILE_BYTES 16384            // 128 rows x 128 B
#define STAGE_BYTES (2 * TILE_BYTES)
#define NSTAGE 3

extern __shared__ __align__(16) char sm_raw[];

__global__ __launch_bounds__(256, 2)
void gemm_f16(const __half* __restrict__ A, const __half* __restrict__ A2,
              int kSplit, int lda,
              const int* __restrict__ gidx,
              const __half* __restrict__ W, int ldw,
              const float* __restrict__ bias,
              const float* __restrict__ addsrc,
              float* __restrict__ C, __half* __restrict__ C16, int ldc,
              int M, int Ncols, int K, int act)
{
    const int tid = threadIdx.x;
    const int wid = tid >> 5;
    const int lane = tid & 31;
    const int bm = blockIdx.x * GBM;
    const int bn = blockIdx.y * GBN;
    const int warp_m = (wid >> 2) * 64;
    const int warp_n = (wid & 3) * 32;

    // loader role: row = tid>>1, 4 x 16B cols at kHalf*4 + j
    const int ldRow = tid >> 1;
    const int kHalf = tid & 1;

    const bool aValid = (bm + ldRow < M);
    int aR = aValid ? (bm + ldRow) : 0;
    if (gidx) aR = __ldg(&gidx[aValid ? bm + ldRow : 0]);
    const __half* aBase = A + (size_t)aR * lda;
    const __half* aBase2 = A2 ? (A2 + (size_t)aR * lda) : nullptr;
    const bool bValid = (bn + ldRow < Ncols);
    const __half* bBase = W + (size_t)(bValid ? bn + ldRow : 0) * ldw;

    const uint32_t smemBase = (uint32_t)__cvta_generic_to_shared(sm_raw);
    const int nCh = (K + GBK - 1) / GBK;
    const int ldSwz = (ldRow & 7);

    float acc[4][4][4];
    #pragma unroll
    for (int mt = 0; mt < 4; mt++)
        #pragma unroll
        for (int nt = 0; nt < 4; nt++)
            #pragma unroll
            for (int j = 0; j < 4; j++) acc[mt][nt][j] = 0.f;

    auto issueStage = [&](int ch, int stage) {
        if (ch < nCh) {
            const uint32_t aDst = smemBase + stage * STAGE_BYTES + ldRow * 128;
            const uint32_t bDst = aDst + TILE_BYTES;
            #pragma unroll
            for (int j = 0; j < 4; j++) {
                const int c = kHalf * 4 + j;          // 16B col 0..7
                const int k = ch * GBK + c * 8;       // fp16 col
                const int rem = K - k;
                const int nb = (rem >= 8) ? 16 : (rem > 0 ? rem * 2 : 0);
                const __half* ap = (k < kSplit) ? (aBase + k)
                                                : (aBase2 + (k - kSplit));
                const uint32_t sw = (uint32_t)((c ^ ldSwz) << 4);
                cp16(aDst + sw, ap, aValid ? nb : 0);
                cp16(bDst + sw, bBase + k, bValid ? nb : 0);
            }
        }
        cp_commit();
    };

    // ldmatrix address prep (per-thread constants)
    const int l8 = lane & 7;
    int aRowB[4], aSwz[4];
    #pragma unroll
    for (int mt = 0; mt < 4; mt++) {
        int row = warp_m + mt * 16 + l8 + ((lane >> 3) & 1) * 8;
        aRowB[mt] = row * 128;
        aSwz[mt] = row & 7;
    }
    const int aColAdd = lane >> 4;            // 0/1
    int bRowB[2], bSwz[2];
    #pragma unroll
    for (int pr = 0; pr < 2; pr++) {
        int row = warp_n + pr * 16 + l8 + ((lane >> 4) & 1) * 8;
        bRowB[pr] = row * 128;
        bSwz[pr] = row & 7;
    }
    const int bColAdd = (lane >> 3) & 1;

    auto computeStage = [&](int stage) {
        const uint32_t aTile = smemBase + stage * STAGE_BYTES;
        const uint32_t bTile = aTile + TILE_BYTES;
        #pragma unroll
        for (int ks = 0; ks < 4; ks++) {
            uint32_t af[4][4], bf[4][2];
            const int colA = ks * 2 + aColAdd;
            #pragma unroll
            for (int mt = 0; mt < 4; mt++)
                ldsm4(af[mt], aTile + aRowB[mt] + ((colA ^ aSwz[mt]) << 4));
            const int colB = ks * 2 + bColAdd;
            #pragma unroll
            for (int pr = 0; pr < 2; pr++) {
                uint32_t r[4];
                ldsm4(r, bTile + bRowB[pr] + ((colB ^ bSwz[pr]) << 4));
                bf[2 * pr][0] = r[0]; bf[2 * pr][1] = r[1];
                bf[2 * pr + 1][0] = r[2]; bf[2 * pr + 1][1] = r[3];
            }
            #pragma unroll
            for (int mt = 0; mt < 4; mt++)
                #pragma unroll
                for (int nt = 0; nt < 4; nt++)
                    mma_f16(acc[mt][nt], af[mt], bf[nt]);
        }
    };

    issueStage(0, 0);
    issueStage(1, 1);
    for (int ch = 0; ch < nCh; ch++) {
        cp_wait1();
        __syncthreads();
        computeStage(ch % NSTAGE);
        issueStage(ch + 2, (ch + 2) % NSTAGE);
    }

    // ---- epilogue ----
    #pragma unroll
    for (int mt = 0; mt < 4; mt++) {
        int row = bm + warp_m + mt * 16 + (lane >> 2);
        #pragma unroll
        for (int nt = 0; nt < 4; nt++) {
            int col = bn + warp_n + nt * 8 + 2 * (lane & 3);
            if (col >= Ncols) continue;
            float b0 = __ldg(&bias[col]);
            float b1 = __ldg(&bias[col + 1]);
            #pragma unroll
            for (int half = 0; half < 2; half++) {
                int r = row + half * 8;
                if (r >= M) continue;
                float v0 = acc[mt][nt][half * 2 + 0] + b0;
                float v1 = acc[mt][nt][half * 2 + 1] + b1;
                if (act) {
                    v0 = (v0 > 0.f) ? v0 : 0.1f * v0;
                    v1 = (v1 > 0.f) ? v1 : 0.1f * v1;
                }
                if (addsrc) {
                    const float2 s = *(const float2*)&addsrc[(size_t)r * ldc + col];
                    v0 += s.x; v1 += s.y;
                }
                if (C)
                    *(float2*)&C[(size_t)r * ldc + col] = make_float2(v0, v1);
                if (C16)
                    *(__half2*)&C16[(size_t)r * ldc + col] =
                        __floats2half2_rn(v0, v1);
            }
        }
    }
}

// ---------------------------------------------------------------------------
extern "C" void kernel_launch(void* const* d_in, const int* in_sizes, int n_in,
                              void* d_out, int out_size) {
    const int*   node_ids = (const int*)  d_in[0];
    const float* content  = (const float*)d_in[1];
    const int*   src      = (const int*)  d_in[2];
    const int*   dst      = (const int*)  d_in[3];
    const float* emb      = (const float*)d_in[4];
    const float* W_exp    = (const float*)d_in[5];
    const float* b_exp    = (const float*)d_in[6];
    const float* W_p1     = (const float*)d_in[7];
    const float* b_p1     = (const float*)d_in[8];
    const float* W_p2     = (const float*)d_in[9];
    const float* b_p2     = (const float*)d_in[10];
    const float* W_conv   = (const float*)d_in[11];
    const float* b_conv   = (const float*)d_in[12];
    const float* Wo1      = (const float*)d_in[13];
    const float* bo1      = (const float*)d_in[14];
    const float* Wo2      = (const float*)d_in[15];
    const float* bo2      = (const float*)d_in[16];
    float* out = (float*)d_out;

    const int N  = in_sizes[0];
    const int E  = in_sizes[2];
    const int NC = in_sizes[1] / N;                 // 300
    const int ED = in_sizes[4] / (N + 1);           // 64
    const int F  = in_sizes[5] / ED;                // 256
    const int L  = in_sizes[11] / (F * 2 * F);      // 3

    float *p_h, *p_hn;
    __half *p_h16, *p_hn16, *p_hagg16, *p_tmp16, *p_emb16, *p_c16;
    __half *p_we, *p_wp1, *p_wp2, *p_wc, *p_wo1, *p_wo2;
    cudaGetSymbolAddress((void**)&p_h, g_h);
    cudaGetSymbolAddress((void**)&p_hn, g_hn);
    cudaGetSymbolAddress((void**)&p_h16, g_h16);
    cudaGetSymbolAddress((void**)&p_hn16, g_hn16);
    cudaGetSymbolAddress((void**)&p_hagg16, g_hagg16);
    cudaGetSymbolAddress((void**)&p_tmp16, g_tmp16);
    cudaGetSymbolAddress((void**)&p_emb16, g_emb16);
    cudaGetSymbolAddress((void**)&p_c16, g_c16);
    cudaGetSymbolAddress((void**)&p_we, g_we16);
    cudaGetSymbolAddress((void**)&p_wp1, g_wp1);
    cudaGetSymbolAddress((void**)&p_wp2, g_wp2);
    cudaGetSymbolAddress((void**)&p_wc, g_wc16);
    cudaGetSymbolAddress((void**)&p_wo1, g_wo1);
    cudaGetSymbolAddress((void**)&p_wo2, g_wo2);

    const int SMEM = NSTAGE * STAGE_BYTES;  // 98304
    cudaFuncSetAttribute(gemm_f16, cudaFuncAttributeMaxDynamicSharedMemorySize, SMEM);

    // ---- fp32 -> fp16 conversions ----
    cvt_kernel<<<512, 256>>>(emb, ED, p_emb16, ED, N + 1, ED);
    cvt_kernel<<<2048, 256>>>(content, NC, p_c16, PADC, N, NC);
    cvt_kernel<<<64, 256>>>(W_exp, ED, p_we, ED, F, ED);
    cvt_kernel<<<128, 256>>>(W_p1, NC, p_wp1, PADC, NC, NC);
    cvt_kernel<<<128, 256>>>(W_p2, NC, p_wp2, PADC, F, NC);
    cvt_kernel<<<256, 256>>>(W_conv, 2 * F, p_wc, 2 * F, L * F, 2 * F);
    cvt_kernel<<<128, 256>>>(Wo1, F, p_wo1, F, (L - 1) * F, F);
    cvt_kernel<<<128, 256>>>(Wo2, F, p_wo2, F, (L - 1) * F, F);

    // ---- CSR build ----
    zero_deg_kernel<<<(N + 255) / 256, 256>>>(N);
    count_deg_kernel<<<1024, 256>>>(dst, E);
    scan_kernel<<<1, 1024>>>(N);
    scatter_kernel<<<1024, 256>>>(src, dst, E);

    const int gmx = (N + GBM - 1) / GBM;
    auto gy = [](int n) { return (n + GBN - 1) / GBN; };
    const int KBIG = 1 << 30;

    // ---- initial representation ----
    // h = lrelu(emb16[ids] @ We^T + be)          -> fp32 g_h
    gemm_f16<<<dim3(gmx, gy(F)), 256, SMEM>>>(
        p_emb16, nullptr, KBIG, ED, node_ids, p_we, ED, b_exp, nullptr,
        p_h, nullptr, F, N, F, ED, 1);
    // tmp16 = lrelu(content16 @ Wp1^T + bp1)     -> fp16 (ld PADC)
    gemm_f16<<<dim3(gmx, gy(NC)), 256, SMEM>>>(
        p_c16, nullptr, KBIG, PADC, nullptr, p_wp1, PADC, b_p1, nullptr,
        nullptr, p_tmp16, PADC, N, NC, PADC, 1);
    // h16 = fp16( lrelu(tmp16 @ Wp2^T + bp2) + h )
    gemm_f16<<<dim3(gmx, gy(F)), 256, SMEM>>>(
        p_tmp16, nullptr, KBIG, PADC, nullptr, p_wp2, PADC, b_p2, p_h,
        nullptr, p_h16, F, N, F, PADC, 1);

    // ---- layers ----
    for (int i = 0; i < L; i++) {
        dim3 aggBlk(64, 4);
        aggregate_kernel<<<(N + 3) / 4, aggBlk>>>(N);

        int act = (i < L - 1) ? 1 : 0;
        // hn = act([h16 | hagg16] @ Wc^T + bc)   -> fp32 g_hn
        gemm_f16<<<dim3(gmx, gy(F)), 256, SMEM>>>(
            p_h16, p_hagg16, F, F, nullptr,
            p_wc + (size_t)i * F * 2 * F, 2 * F,
            b_conv + (size_t)i * F, nullptr,
            p_hn, nullptr, F, N, F, 2 * F, act);

        if (i < L - 1) {
            l2norm16_kernel<<<N, F>>>(p_hn, p_hn16, N);
            // tmp16 = fp16(lrelu(hn16 @ Wo1^T + bo1))
            gemm_f16<<<dim3(gmx, gy(F)), 256, SMEM>>>(
                p_hn16, nullptr, KBIG, F, nullptr,
                p_wo1 + (size_t)i * F * F, F,
                bo1 + (size_t)i * F, nullptr,
                nullptr, p_tmp16, PADC, N, F, F, 1);
            // h16 = fp16(tmp16 @ Wo2^T + bo2)
            gemm_f16<<<dim3(gmx, gy(F)), 256, SMEM>>>(
                p_tmp16, nullptr, KBIG, PADC, nullptr,
                p_wo2 + (size_t)i * F * F, F,
                bo2 + (size_t)i * F, nullptr,
                nullptr, p_h16, F, N, F, F, 0);
        } else {
            l2norm_kernel<<<N, F>>>(p_hn, out, N);
        }
    }
}